// round 1
// baseline (speedup 1.0000x reference)
#include <cuda_runtime.h>
#include <math.h>

// Problem constants
#define BB 8
#define CC 512
#define NN 4096
#define MM 1024

// Scratch (no cudaMalloc allowed) — static device globals.
__device__ float g_Q[(size_t)BB * CC * NN];   // 64 MB
__device__ float g_K[(size_t)BB * CC * MM];   // 16 MB
__device__ float g_V[(size_t)BB * CC * MM];   // 16 MB
__device__ float g_E[(size_t)BB * NN * MM];   // 128 MB (energy -> attention in place)

// ---------------------------------------------------------------------------
// Kernel 1: 1x1 conv == per-batch GEMM: out[b,o,x] = sum_c W[o,c] * in[b,c,x]
// Tile 64(o) x 64(x), KT=16, 256 threads, 4x4 microtile.
// ---------------------------------------------------------------------------
__global__ void __launch_bounds__(256) conv1x1_kernel(
    const float* __restrict__ W, const float* __restrict__ in,
    float* __restrict__ out, int X)
{
    __shared__ float Ws[16][65];   // [c][o] (transposed store -> pad)
    __shared__ float Is[16][64];   // [c][x]

    const int b  = blockIdx.z;
    const int o0 = blockIdx.y * 64;
    const int x0 = blockIdx.x * 64;
    const float* inb = in + (size_t)b * CC * X;

    const int t  = threadIdx.x;
    const int ty = t >> 4;         // 0..15 -> o group
    const int tx = t & 15;         // 0..15 -> x group

    const int wrow = t >> 2;        // 0..63 (o)
    const int wcol = (t & 3) * 4;   // 0,4,8,12 (c)
    const int irow = t >> 4;        // 0..15 (c)
    const int icol = (t & 15) * 4;  // 0..60 (x)

    float acc[4][4] = {};

    for (int c0 = 0; c0 < CC; c0 += 16) {
        float4 w = *(const float4*)&W[(size_t)(o0 + wrow) * CC + c0 + wcol];
        Ws[wcol + 0][wrow] = w.x;
        Ws[wcol + 1][wrow] = w.y;
        Ws[wcol + 2][wrow] = w.z;
        Ws[wcol + 3][wrow] = w.w;
        *(float4*)&Is[irow][icol] =
            *(const float4*)&inb[(size_t)(c0 + irow) * X + x0 + icol];
        __syncthreads();

        #pragma unroll
        for (int c = 0; c < 16; c++) {
            float a0 = Ws[c][ty * 4 + 0];
            float a1 = Ws[c][ty * 4 + 1];
            float a2 = Ws[c][ty * 4 + 2];
            float a3 = Ws[c][ty * 4 + 3];
            float4 bb = *(const float4*)&Is[c][tx * 4];
            acc[0][0] += a0 * bb.x; acc[0][1] += a0 * bb.y; acc[0][2] += a0 * bb.z; acc[0][3] += a0 * bb.w;
            acc[1][0] += a1 * bb.x; acc[1][1] += a1 * bb.y; acc[1][2] += a1 * bb.z; acc[1][3] += a1 * bb.w;
            acc[2][0] += a2 * bb.x; acc[2][1] += a2 * bb.y; acc[2][2] += a2 * bb.z; acc[2][3] += a2 * bb.w;
            acc[3][0] += a3 * bb.x; acc[3][1] += a3 * bb.y; acc[3][2] += a3 * bb.z; acc[3][3] += a3 * bb.w;
        }
        __syncthreads();
    }

    float* outb = out + (size_t)b * CC * X;
    #pragma unroll
    for (int i = 0; i < 4; i++) {
        *(float4*)&outb[(size_t)(o0 + ty * 4 + i) * X + x0 + tx * 4] =
            make_float4(acc[i][0], acc[i][1], acc[i][2], acc[i][3]);
    }
}

// ---------------------------------------------------------------------------
// Kernel 2: energy[b,n,m] = (1/sqrt(C)) * sum_c Q[b,c,n] * K[b,c,m]
// TN GEMM: both operands have the contraction dim (c) as slow dim -> coalesced.
// ---------------------------------------------------------------------------
__global__ void __launch_bounds__(256) energy_kernel(
    const float* __restrict__ Q, const float* __restrict__ K,
    float* __restrict__ E)
{
    __shared__ float Qs[16][64];   // [c][n]
    __shared__ float Ks[16][64];   // [c][m]

    const int b  = blockIdx.z;
    const int n0 = blockIdx.y * 64;
    const int m0 = blockIdx.x * 64;
    const float* Qb = Q + (size_t)b * CC * NN;
    const float* Kb = K + (size_t)b * CC * MM;

    const int t  = threadIdx.x;
    const int ty = t >> 4;
    const int tx = t & 15;
    const int row = t >> 4;          // 0..15 (c)
    const int col = (t & 15) * 4;    // 0..60

    float acc[4][4] = {};

    for (int c0 = 0; c0 < CC; c0 += 16) {
        *(float4*)&Qs[row][col] = *(const float4*)&Qb[(size_t)(c0 + row) * NN + n0 + col];
        *(float4*)&Ks[row][col] = *(const float4*)&Kb[(size_t)(c0 + row) * MM + m0 + col];
        __syncthreads();

        #pragma unroll
        for (int c = 0; c < 16; c++) {
            float a0 = Qs[c][ty * 4 + 0];
            float a1 = Qs[c][ty * 4 + 1];
            float a2 = Qs[c][ty * 4 + 2];
            float a3 = Qs[c][ty * 4 + 3];
            float4 bb = *(const float4*)&Ks[c][tx * 4];
            acc[0][0] += a0 * bb.x; acc[0][1] += a0 * bb.y; acc[0][2] += a0 * bb.z; acc[0][3] += a0 * bb.w;
            acc[1][0] += a1 * bb.x; acc[1][1] += a1 * bb.y; acc[1][2] += a1 * bb.z; acc[1][3] += a1 * bb.w;
            acc[2][0] += a2 * bb.x; acc[2][1] += a2 * bb.y; acc[2][2] += a2 * bb.z; acc[2][3] += a2 * bb.w;
            acc[3][0] += a3 * bb.x; acc[3][1] += a3 * bb.y; acc[3][2] += a3 * bb.z; acc[3][3] += a3 * bb.w;
        }
        __syncthreads();
    }

    const float rscale = 0.04419417382415922f;  // 1/sqrt(512)
    float* Eb = E + (size_t)b * NN * MM;
    #pragma unroll
    for (int i = 0; i < 4; i++) {
        *(float4*)&Eb[(size_t)(n0 + ty * 4 + i) * MM + m0 + tx * 4] =
            make_float4(acc[i][0] * rscale, acc[i][1] * rscale,
                        acc[i][2] * rscale, acc[i][3] * rscale);
    }
}

// ---------------------------------------------------------------------------
// Kernel 3: in-place softmax over last dim (M=1024). One CTA of 256 per row.
// ---------------------------------------------------------------------------
__global__ void __launch_bounds__(256) softmax_kernel(float* __restrict__ E)
{
    float4* row = (float4*)(E + (size_t)blockIdx.x * MM);
    const int t = threadIdx.x;
    float4 v = row[t];

    __shared__ float rmax[8];
    __shared__ float rsum[8];

    float mx = fmaxf(fmaxf(v.x, v.y), fmaxf(v.z, v.w));
    #pragma unroll
    for (int o = 16; o > 0; o >>= 1)
        mx = fmaxf(mx, __shfl_xor_sync(0xffffffffu, mx, o));
    if ((t & 31) == 0) rmax[t >> 5] = mx;
    __syncthreads();
    mx = rmax[0];
    #pragma unroll
    for (int i = 1; i < 8; i++) mx = fmaxf(mx, rmax[i]);

    float e0 = __expf(v.x - mx);
    float e1 = __expf(v.y - mx);
    float e2 = __expf(v.z - mx);
    float e3 = __expf(v.w - mx);
    float s = e0 + e1 + e2 + e3;
    #pragma unroll
    for (int o = 16; o > 0; o >>= 1)
        s += __shfl_xor_sync(0xffffffffu, s, o);
    if ((t & 31) == 0) rsum[t >> 5] = s;
    __syncthreads();
    s = rsum[0];
    #pragma unroll
    for (int i = 1; i < 8; i++) s += rsum[i];

    float inv = 1.0f / s;
    row[t] = make_float4(e0 * inv, e1 * inv, e2 * inv, e3 * inv);
}

// ---------------------------------------------------------------------------
// Kernel 4: out[b,c,n] += sum_m V[b,c,m] * P[b,n,m]   (NT GEMM, K=M=1024)
// out already holds skip. Tile 64(c) x 64(n), KT=16(m).
// ---------------------------------------------------------------------------
__global__ void __launch_bounds__(256) attnv_kernel(
    const float* __restrict__ P, const float* __restrict__ V,
    float* __restrict__ out)
{
    __shared__ float Vs[16][65];   // [m][c]
    __shared__ float Ps[16][65];   // [m][n]

    const int b  = blockIdx.z;
    const int c0 = blockIdx.y * 64;
    const int n0 = blockIdx.x * 64;
    const float* Vb = V + (size_t)b * CC * MM;
    const float* Pb = P + (size_t)b * NN * MM;

    const int t  = threadIdx.x;
    const int ty = t >> 4;          // c group
    const int tx = t & 15;          // n group
    const int lrow = t >> 2;        // 0..63
    const int lcol = (t & 3) * 4;   // 0,4,8,12 (m)

    float acc[4][4] = {};

    for (int m0 = 0; m0 < MM; m0 += 16) {
        float4 vv = *(const float4*)&Vb[(size_t)(c0 + lrow) * MM + m0 + lcol];
        Vs[lcol + 0][lrow] = vv.x;
        Vs[lcol + 1][lrow] = vv.y;
        Vs[lcol + 2][lrow] = vv.z;
        Vs[lcol + 3][lrow] = vv.w;
        float4 pp = *(const float4*)&Pb[(size_t)(n0 + lrow) * MM + m0 + lcol];
        Ps[lcol + 0][lrow] = pp.x;
        Ps[lcol + 1][lrow] = pp.y;
        Ps[lcol + 2][lrow] = pp.z;
        Ps[lcol + 3][lrow] = pp.w;
        __syncthreads();

        #pragma unroll
        for (int m = 0; m < 16; m++) {
            float a0 = Vs[m][ty * 4 + 0];
            float a1 = Vs[m][ty * 4 + 1];
            float a2 = Vs[m][ty * 4 + 2];
            float a3 = Vs[m][ty * 4 + 3];
            float b0 = Ps[m][tx * 4 + 0];
            float b1 = Ps[m][tx * 4 + 1];
            float b2 = Ps[m][tx * 4 + 2];
            float b3 = Ps[m][tx * 4 + 3];
            acc[0][0] += a0 * b0; acc[0][1] += a0 * b1; acc[0][2] += a0 * b2; acc[0][3] += a0 * b3;
            acc[1][0] += a1 * b0; acc[1][1] += a1 * b1; acc[1][2] += a1 * b2; acc[1][3] += a1 * b3;
            acc[2][0] += a2 * b0; acc[2][1] += a2 * b1; acc[2][2] += a2 * b2; acc[2][3] += a2 * b3;
            acc[3][0] += a3 * b0; acc[3][1] += a3 * b1; acc[3][2] += a3 * b2; acc[3][3] += a3 * b3;
        }
        __syncthreads();
    }

    float* outb = out + (size_t)b * CC * NN;
    #pragma unroll
    for (int i = 0; i < 4; i++) {
        size_t idx = (size_t)(c0 + ty * 4 + i) * NN + n0 + tx * 4;
        float4 ov = *(float4*)&outb[idx];
        ov.x += acc[i][0];
        ov.y += acc[i][1];
        ov.z += acc[i][2];
        ov.w += acc[i][3];
        *(float4*)&outb[idx] = ov;
    }
}

// ---------------------------------------------------------------------------
// Launch
// inputs (metadata order): pcd_up [B,C,N], pcd_down [B,C,M],
//                          Wq, Wk, Wv, Wskip  [C,C]
// output: [B,C,N] float32
// ---------------------------------------------------------------------------
extern "C" void kernel_launch(void* const* d_in, const int* in_sizes, int n_in,
                              void* d_out, int out_size)
{
    const float* pcd_up   = (const float*)d_in[0];
    const float* pcd_down = (const float*)d_in[1];
    const float* Wq       = (const float*)d_in[2];
    const float* Wk       = (const float*)d_in[3];
    const float* Wv       = (const float*)d_in[4];
    const float* Wskip    = (const float*)d_in[5];
    float* out = (float*)d_out;

    float *Q, *K, *V, *E;
    cudaGetSymbolAddress((void**)&Q, g_Q);
    cudaGetSymbolAddress((void**)&K, g_K);
    cudaGetSymbolAddress((void**)&V, g_V);
    cudaGetSymbolAddress((void**)&E, g_E);

    // Projections
    conv1x1_kernel<<<dim3(NN / 64, CC / 64, BB), 256>>>(Wq,    pcd_up,   Q,   NN);
    conv1x1_kernel<<<dim3(NN / 64, CC / 64, BB), 256>>>(Wskip, pcd_up,   out, NN);
    conv1x1_kernel<<<dim3(MM / 64, CC / 64, BB), 256>>>(Wk,    pcd_down, K,   MM);
    conv1x1_kernel<<<dim3(MM / 64, CC / 64, BB), 256>>>(Wv,    pcd_down, V,   MM);

    // energy = q^T k / sqrt(C)
    energy_kernel<<<dim3(MM / 64, NN / 64, BB), 256>>>(Q, K, E);

    // softmax over M (in place)
    softmax_kernel<<<BB * NN, 256>>>(E);

    // out += attention @ v^T
    attnv_kernel<<<dim3(NN / 64, CC / 64, BB), 256>>>(E, V, out);
}

// round 3
// speedup vs baseline: 2.0887x; 2.0887x over previous
#include <cuda_runtime.h>
#include <cuda_bf16.h>
#include <cstdint>
#include <math.h>

// Problem constants
#define BB 8
#define CC 512
#define NN 4096
#define MM 1024

// Scratch (no cudaMalloc allowed) — static device globals.
__device__ float g_Q[(size_t)BB * CC * NN];   // 64 MB
__device__ float g_K[(size_t)BB * CC * MM];   // 16 MB
__device__ float g_V[(size_t)BB * CC * MM];   // 16 MB
__device__ float g_E[(size_t)BB * NN * MM];   // 128 MB (energy -> attention in place)

// ---------------------------------------------------------------------------
// bf16x2 pack + hi/lo split helpers
// ---------------------------------------------------------------------------
__device__ __forceinline__ void split_bf16(float x, __nv_bfloat16& h, __nv_bfloat16& l) {
    h = __float2bfloat16_rn(x);
    l = __float2bfloat16_rn(x - __bfloat162float(h));
}

__device__ __forceinline__ uint32_t pack2(__nv_bfloat16 a, __nv_bfloat16 b) {
    __nv_bfloat162 t;
    t.x = a; t.y = b;              // a -> low 16 bits (lower k index)
    return *(uint32_t*)&t;
}

// mma.sync m16n8k16 bf16 -> f32 accum
__device__ __forceinline__ void mma_bf16(float* c, const uint32_t* a,
                                         uint32_t b0, uint32_t b1) {
    asm volatile(
        "mma.sync.aligned.m16n8k16.row.col.f32.bf16.bf16.f32 "
        "{%0,%1,%2,%3}, {%4,%5,%6,%7}, {%8,%9}, {%0,%1,%2,%3};"
        : "+f"(c[0]), "+f"(c[1]), "+f"(c[2]), "+f"(c[3])
        : "r"(a[0]), "r"(a[1]), "r"(a[2]), "r"(a[3]), "r"(b0), "r"(b1));
}

// ---------------------------------------------------------------------------
// Generic tensor-core GEMM with bf16x3 fp32 emulation.
//   D[m, n] (tile 128x128) = scale * sum_k A(m,k) * B(n,k)   [+ D if ACCUM]
// TA=false: A stored [m, k] (k-fast).  TA=true: A stored [k, m] (m-fast).
// Same for B with n. Grid: (Ntiles, Mtiles, batch). 256 threads.
// ---------------------------------------------------------------------------
#define KT 32
#define SP 40   // smem pitch in bf16 halfwords (= 20 words, conflict-free)

template<bool TA, bool TB, bool ACCUM>
__global__ void __launch_bounds__(256) tc_gemm(
    const float* __restrict__ A, const float* __restrict__ B, float* __restrict__ D,
    int lda, int ldb, int ldd,
    size_t strA, size_t strB, size_t strD,
    int Kdim, float scale)
{
    __shared__ __nv_bfloat16 Ah[128][SP];
    __shared__ __nv_bfloat16 Al[128][SP];
    __shared__ __nv_bfloat16 Bh[128][SP];
    __shared__ __nv_bfloat16 Bl[128][SP];

    const int tid  = threadIdx.x;
    const int wid  = tid >> 5;
    const int lane = tid & 31;
    const int g    = lane >> 2;
    const int t4   = lane & 3;
    const int wm   = (wid >> 1) * 32;   // warp tile row offset (m)
    const int wn   = (wid & 1) * 64;    // warp tile col offset (n)

    const int bz = blockIdx.z;
    const int m0 = blockIdx.y * 128;
    const int n0 = blockIdx.x * 128;

    A += (size_t)bz * strA;
    B += (size_t)bz * strB;
    D += (size_t)bz * strD;

    float acc[2][8][4] = {};
    float4 pa[4], pb[4];

    const int nstages = Kdim / KT;

    // ---- load tile (global -> regs) ----
    auto load_tile = [&](int k0) {
        #pragma unroll
        for (int i = 0; i < 4; i++) {
            int f = tid + i * 256;
            if (!TA) {
                int row = f >> 3, kq = f & 7;
                pa[i] = *(const float4*)&A[(size_t)(m0 + row) * lda + k0 + kq * 4];
            } else {
                int krow = f & 31, mq = f >> 5;
                pa[i] = *(const float4*)&A[(size_t)(k0 + krow) * lda + m0 + mq * 4];
            }
        }
        #pragma unroll
        for (int i = 0; i < 4; i++) {
            int f = tid + i * 256;
            if (!TB) {
                int row = f >> 3, kq = f & 7;
                pb[i] = *(const float4*)&B[(size_t)(n0 + row) * ldb + k0 + kq * 4];
            } else {
                int krow = f & 31, nq = f >> 5;
                pb[i] = *(const float4*)&B[(size_t)(k0 + krow) * ldb + n0 + nq * 4];
            }
        }
    };

    // ---- store tile (regs -> split hi/lo smem) ----
    auto store_tile = [&]() {
        #pragma unroll
        for (int i = 0; i < 4; i++) {
            int f = tid + i * 256;
            float v[4] = {pa[i].x, pa[i].y, pa[i].z, pa[i].w};
            __nv_bfloat16 h[4], l[4];
            #pragma unroll
            for (int e = 0; e < 4; e++) split_bf16(v[e], h[e], l[e]);
            if (!TA) {
                int row = f >> 3, kq = f & 7;
                *(uint2*)&Ah[row][kq * 4] =
                    make_uint2(pack2(h[0], h[1]), pack2(h[2], h[3]));
                *(uint2*)&Al[row][kq * 4] =
                    make_uint2(pack2(l[0], l[1]), pack2(l[2], l[3]));
            } else {
                int krow = f & 31, mq = f >> 5;
                #pragma unroll
                for (int j = 0; j < 4; j++) {
                    Ah[mq * 4 + j][krow] = h[j];
                    Al[mq * 4 + j][krow] = l[j];
                }
            }
        }
        #pragma unroll
        for (int i = 0; i < 4; i++) {
            int f = tid + i * 256;
            float v[4] = {pb[i].x, pb[i].y, pb[i].z, pb[i].w};
            __nv_bfloat16 h[4], l[4];
            #pragma unroll
            for (int e = 0; e < 4; e++) split_bf16(v[e], h[e], l[e]);
            if (!TB) {
                int row = f >> 3, kq = f & 7;
                *(uint2*)&Bh[row][kq * 4] =
                    make_uint2(pack2(h[0], h[1]), pack2(h[2], h[3]));
                *(uint2*)&Bl[row][kq * 4] =
                    make_uint2(pack2(l[0], l[1]), pack2(l[2], l[3]));
            } else {
                int krow = f & 31, nq = f >> 5;
                #pragma unroll
                for (int j = 0; j < 4; j++) {
                    Bh[nq * 4 + j][krow] = h[j];
                    Bl[nq * 4 + j][krow] = l[j];
                }
            }
        }
    };

    // ---- compute one KT tile from smem ----
    auto compute = [&]() {
        #pragma unroll
        for (int kp = 0; kp < 2; kp++) {
            const int cp = kp * 8 + t4;   // k-pair index
            uint32_t ah[2][4], al[2][4];
            #pragma unroll
            for (int ma = 0; ma < 2; ma++) {
                int r = wm + ma * 16 + g;
                ah[ma][0] = *(const uint32_t*)&Ah[r][2 * cp];
                ah[ma][1] = *(const uint32_t*)&Ah[r + 8][2 * cp];
                ah[ma][2] = *(const uint32_t*)&Ah[r][2 * (cp + 4)];
                ah[ma][3] = *(const uint32_t*)&Ah[r + 8][2 * (cp + 4)];
                al[ma][0] = *(const uint32_t*)&Al[r][2 * cp];
                al[ma][1] = *(const uint32_t*)&Al[r + 8][2 * cp];
                al[ma][2] = *(const uint32_t*)&Al[r][2 * (cp + 4)];
                al[ma][3] = *(const uint32_t*)&Al[r + 8][2 * (cp + 4)];
            }
            #pragma unroll
            for (int na = 0; na < 8; na++) {
                int rn_ = wn + na * 8 + g;
                uint32_t bh0 = *(const uint32_t*)&Bh[rn_][2 * cp];
                uint32_t bh1 = *(const uint32_t*)&Bh[rn_][2 * (cp + 4)];
                uint32_t bl0 = *(const uint32_t*)&Bl[rn_][2 * cp];
                uint32_t bl1 = *(const uint32_t*)&Bl[rn_][2 * (cp + 4)];
                #pragma unroll
                for (int ma = 0; ma < 2; ma++) {
                    mma_bf16(acc[ma][na], ah[ma], bh0, bh1);  // hi*hi
                    mma_bf16(acc[ma][na], ah[ma], bl0, bl1);  // hi*lo
                    mma_bf16(acc[ma][na], al[ma], bh0, bh1);  // lo*hi
                }
            }
        }
    };

    // ---- pipeline: register-prefetch double buffering ----
    load_tile(0);
    store_tile();
    __syncthreads();
    for (int s = 0;;) {
        if (s + 1 < nstages) load_tile((s + 1) * KT);
        compute();
        s++;
        if (s == nstages) break;
        __syncthreads();
        store_tile();
        __syncthreads();
    }

    // ---- epilogue ----
    #pragma unroll
    for (int ma = 0; ma < 2; ma++) {
        #pragma unroll
        for (int na = 0; na < 8; na++) {
            const int r0 = m0 + wm + ma * 16 + g;
            const int cb = n0 + wn + na * 8 + 2 * t4;
            float2 v0 = make_float2(acc[ma][na][0] * scale, acc[ma][na][1] * scale);
            float2 v1 = make_float2(acc[ma][na][2] * scale, acc[ma][na][3] * scale);
            float* p0 = &D[(size_t)r0 * ldd + cb];
            float* p1 = &D[(size_t)(r0 + 8) * ldd + cb];
            if (ACCUM) {
                float2 o0 = *(const float2*)p0;
                float2 o1 = *(const float2*)p1;
                v0.x += o0.x; v0.y += o0.y;
                v1.x += o1.x; v1.y += o1.y;
            }
            *(float2*)p0 = v0;
            *(float2*)p1 = v1;
        }
    }
}

// ---------------------------------------------------------------------------
// Softmax over last dim (M=1024), in place. One CTA of 256 per row.
// ---------------------------------------------------------------------------
__global__ void __launch_bounds__(256) softmax_kernel(float* __restrict__ E)
{
    float4* row = (float4*)(E + (size_t)blockIdx.x * MM);
    const int t = threadIdx.x;
    float4 v = row[t];

    __shared__ float rmax[8];
    __shared__ float rsum[8];

    float mx = fmaxf(fmaxf(v.x, v.y), fmaxf(v.z, v.w));
    #pragma unroll
    for (int o = 16; o > 0; o >>= 1)
        mx = fmaxf(mx, __shfl_xor_sync(0xffffffffu, mx, o));
    if ((t & 31) == 0) rmax[t >> 5] = mx;
    __syncthreads();
    mx = rmax[0];
    #pragma unroll
    for (int i = 1; i < 8; i++) mx = fmaxf(mx, rmax[i]);

    float e0 = __expf(v.x - mx);
    float e1 = __expf(v.y - mx);
    float e2 = __expf(v.z - mx);
    float e3 = __expf(v.w - mx);
    float s = e0 + e1 + e2 + e3;
    #pragma unroll
    for (int o = 16; o > 0; o >>= 1)
        s += __shfl_xor_sync(0xffffffffu, s, o);
    if ((t & 31) == 0) rsum[t >> 5] = s;
    __syncthreads();
    s = rsum[0];
    #pragma unroll
    for (int i = 1; i < 8; i++) s += rsum[i];

    float inv = 1.0f / s;
    row[t] = make_float4(e0 * inv, e1 * inv, e2 * inv, e3 * inv);
}

// ---------------------------------------------------------------------------
// Launch
// inputs: pcd_up [B,C,N], pcd_down [B,C,M], Wq, Wk, Wv, Wskip [C,C]
// output: [B,C,N] float32
// ---------------------------------------------------------------------------
extern "C" void kernel_launch(void* const* d_in, const int* in_sizes, int n_in,
                              void* d_out, int out_size)
{
    const float* pcd_up   = (const float*)d_in[0];
    const float* pcd_down = (const float*)d_in[1];
    const float* Wq       = (const float*)d_in[2];
    const float* Wk       = (const float*)d_in[3];
    const float* Wv       = (const float*)d_in[4];
    const float* Wskip    = (const float*)d_in[5];
    float* out = (float*)d_out;

    float *Q, *K, *V, *E;
    cudaGetSymbolAddress((void**)&Q, g_Q);
    cudaGetSymbolAddress((void**)&K, g_K);
    cudaGetSymbolAddress((void**)&V, g_V);
    cudaGetSymbolAddress((void**)&E, g_E);

    const float rscale = 0.04419417382415922f;  // 1/sqrt(512)

    // Projections: out[o,x] = sum_c W[o,c] * in[c,x]
    // A = W [o,c] (k-fast), B = in [c,x] (transposed), M=o, N=x, K=C
    tc_gemm<false, true, false><<<dim3(NN / 128, CC / 128, BB), 256>>>(
        Wq, pcd_up, Q, CC, NN, NN, 0, (size_t)CC * NN, (size_t)CC * NN, CC, 1.0f);
    tc_gemm<false, true, false><<<dim3(NN / 128, CC / 128, BB), 256>>>(
        Wskip, pcd_up, out, CC, NN, NN, 0, (size_t)CC * NN, (size_t)CC * NN, CC, 1.0f);
    tc_gemm<false, true, false><<<dim3(MM / 128, CC / 128, BB), 256>>>(
        Wk, pcd_down, K, CC, MM, MM, 0, (size_t)CC * MM, (size_t)CC * MM, CC, 1.0f);
    tc_gemm<false, true, false><<<dim3(MM / 128, CC / 128, BB), 256>>>(
        Wv, pcd_down, V, CC, MM, MM, 0, (size_t)CC * MM, (size_t)CC * MM, CC, 1.0f);

    // energy[n,m] = (1/sqrt(C)) sum_c Q[c,n] K[c,m] : both transposed, K=C
    tc_gemm<true, true, false><<<dim3(MM / 128, NN / 128, BB), 256>>>(
        Q, K, E, NN, MM, MM, (size_t)CC * NN, (size_t)CC * MM, (size_t)NN * MM,
        CC, rscale);

    // softmax over M, in place
    softmax_kernel<<<BB * NN, 256>>>(E);

    // out[c,n] += sum_m V[c,m] * P[n,m] : both k-fast, K=M
    tc_gemm<false, false, true><<<dim3(NN / 128, CC / 128, BB), 256>>>(
        V, E, out, MM, MM, NN, (size_t)CC * MM, (size_t)NN * MM, (size_t)CC * NN,
        MM, 1.0f);
}

// round 4
// speedup vs baseline: 2.3749x; 1.1370x over previous
#include <cuda_runtime.h>
#include <cuda_bf16.h>
#include <cstdint>
#include <math.h>

// Problem constants
#define BB 8
#define CC 512
#define NN 4096
#define MM 1024

// Scratch (no cudaMalloc allowed) — static device globals.
__device__ float g_Tup [(size_t)BB * NN * CC];  // pcd_up^T   [B][N][C] 64 MB
__device__ float g_Tdn [(size_t)BB * MM * CC];  // pcd_down^T [B][M][C] 16 MB
__device__ float g_Qt  [(size_t)BB * NN * CC];  // Q^T  [B][N][C] 64 MB
__device__ float g_Kt  [(size_t)BB * MM * CC];  // K^T  [B][M][C] 16 MB
__device__ float g_V   [(size_t)BB * CC * MM];  // V    [B][C][M] 16 MB
__device__ float g_E   [(size_t)BB * NN * MM];  // energy/attn [B][N][M] 128 MB

// ---------------------------------------------------------------------------
// helpers
// ---------------------------------------------------------------------------
__device__ __forceinline__ uint32_t smem_u32(const void* p) {
    uint32_t a;
    asm("{ .reg .u64 t; cvta.to.shared.u64 t, %1; cvt.u32.u64 %0, t; }"
        : "=r"(a) : "l"(p));
    return a;
}

__device__ __forceinline__ void split_bf16(float x, __nv_bfloat16& h, __nv_bfloat16& l) {
    h = __float2bfloat16_rn(x);
    l = __float2bfloat16_rn(x - __bfloat162float(h));
}

__device__ __forceinline__ uint32_t pack2(__nv_bfloat16 a, __nv_bfloat16 b) {
    __nv_bfloat162 t;
    t.x = a; t.y = b;              // a -> low 16 bits (lower k index)
    return *(uint32_t*)&t;
}

__device__ __forceinline__ void mma_bf16(float* c, const uint32_t* a,
                                         uint32_t b0, uint32_t b1) {
    asm volatile(
        "mma.sync.aligned.m16n8k16.row.col.f32.bf16.bf16.f32 "
        "{%0,%1,%2,%3}, {%4,%5,%6,%7}, {%8,%9}, {%0,%1,%2,%3};"
        : "+f"(c[0]), "+f"(c[1]), "+f"(c[2]), "+f"(c[3])
        : "r"(a[0]), "r"(a[1]), "r"(a[2]), "r"(a[3]), "r"(b0), "r"(b1));
}

__device__ __forceinline__ void ldsm4(uint32_t& r0, uint32_t& r1,
                                      uint32_t& r2, uint32_t& r3, uint32_t addr) {
    asm volatile("ldmatrix.sync.aligned.m8n8.x4.shared.b16 {%0,%1,%2,%3}, [%4];"
                 : "=r"(r0), "=r"(r1), "=r"(r2), "=r"(r3) : "r"(addr));
}

// ---------------------------------------------------------------------------
// fp32 transpose: out[x][r] = in[r][x], per batch. 32x32 tiles, 256 threads.
// ---------------------------------------------------------------------------
__global__ void __launch_bounds__(256) transpose_kernel(
    const float* __restrict__ in, float* __restrict__ out, int rows, int cols)
{
    __shared__ float t[32][33];
    const int b = blockIdx.z;
    in  += (size_t)b * rows * cols;
    out += (size_t)b * rows * cols;
    const int r0 = blockIdx.y * 32, c0 = blockIdx.x * 32;
    const int tx = threadIdx.x & 31, ty = threadIdx.x >> 5;
    #pragma unroll
    for (int i = 0; i < 32; i += 8)
        t[ty + i][tx] = in[(size_t)(r0 + ty + i) * cols + c0 + tx];
    __syncthreads();
    #pragma unroll
    for (int i = 0; i < 32; i += 8)
        out[(size_t)(c0 + ty + i) * rows + r0 + tx] = t[tx][ty + i];
}

// ---------------------------------------------------------------------------
// Tensor-core GEMM, bf16x3 fp32 emulation, all operands k-fast.
//   D[m, n] (tile 128x128) = scale * sum_k A[m][k] * B[n][k]   [+ D if ACCUM]
// Smem: rows of 32 halfwords (64 B), XOR chunk swizzle:
//   phys(row, k) = ((k>>3) ^ ((row>>1)&3))*8 + (k&7)
// Conflict-free for STS.64 staging and LDSM row addressing.
// ---------------------------------------------------------------------------
#define KT 32

template<bool ACCUM>
__global__ void __launch_bounds__(256) tc_gemm(
    const float* __restrict__ A, const float* __restrict__ B, float* __restrict__ D,
    int lda, int ldb, int ldd,
    size_t strA, size_t strB, size_t strD,
    int Kdim, float scale)
{
    __shared__ __nv_bfloat16 Ah[128 * 32];
    __shared__ __nv_bfloat16 Al[128 * 32];
    __shared__ __nv_bfloat16 Bh[128 * 32];
    __shared__ __nv_bfloat16 Bl[128 * 32];

    const int tid  = threadIdx.x;
    const int wid  = tid >> 5;
    const int lane = tid & 31;
    const int g    = lane >> 2;
    const int t4   = lane & 3;
    const int wm   = (wid >> 1) * 32;   // warp m offset
    const int wn   = (wid & 1) * 64;    // warp n offset

    const int bz = blockIdx.z;
    const int m0 = blockIdx.y * 128;
    const int n0 = blockIdx.x * 128;

    A += (size_t)bz * strA;
    B += (size_t)bz * strB;
    D += (size_t)bz * strD;

    const uint32_t baseAh = smem_u32(Ah);
    const uint32_t baseAl = smem_u32(Al);
    const uint32_t baseBh = smem_u32(Bh);
    const uint32_t baseBl = smem_u32(Bl);

    float acc[2][8][4] = {};
    float4 pa[4], pb[4];

    const int nstages = Kdim / KT;

    // ---- global -> regs ----
    auto load_tile = [&](int k0) {
        #pragma unroll
        for (int i = 0; i < 4; i++) {
            int f = tid + i * 256;
            int row = f >> 3, kq = f & 7;
            pa[i] = *(const float4*)&A[(size_t)(m0 + row) * lda + k0 + kq * 4];
            pb[i] = *(const float4*)&B[(size_t)(n0 + row) * ldb + k0 + kq * 4];
        }
    };

    // ---- regs -> split hi/lo smem (swizzled) ----
    auto store_tile = [&]() {
        #pragma unroll
        for (int i = 0; i < 4; i++) {
            int f = tid + i * 256;
            int row = f >> 3, kq = f & 7;
            // logical k = kq*4 .. kq*4+3; chunk = kq>>1, sub = (kq&1)*4
            int phys = (((kq >> 1) ^ ((row >> 1) & 3)) << 3) + (kq & 1) * 4;
            int off = row * 32 + phys;
            {
                float v[4] = {pa[i].x, pa[i].y, pa[i].z, pa[i].w};
                __nv_bfloat16 h[4], l[4];
                #pragma unroll
                for (int e = 0; e < 4; e++) split_bf16(v[e], h[e], l[e]);
                *(uint2*)&Ah[off] = make_uint2(pack2(h[0], h[1]), pack2(h[2], h[3]));
                *(uint2*)&Al[off] = make_uint2(pack2(l[0], l[1]), pack2(l[2], l[3]));
            }
            {
                float v[4] = {pb[i].x, pb[i].y, pb[i].z, pb[i].w};
                __nv_bfloat16 h[4], l[4];
                #pragma unroll
                for (int e = 0; e < 4; e++) split_bf16(v[e], h[e], l[e]);
                *(uint2*)&Bh[off] = make_uint2(pack2(h[0], h[1]), pack2(h[2], h[3]));
                *(uint2*)&Bl[off] = make_uint2(pack2(l[0], l[1]), pack2(l[2], l[3]));
            }
        }
    };

    // ---- one KT tile of MMAs from smem ----
    auto compute = [&]() {
        #pragma unroll
        for (int kp = 0; kp < 2; kp++) {
            uint32_t ah[2][4], al[2][4];
            #pragma unroll
            for (int ma = 0; ma < 2; ma++) {
                // tiles: t0=(m0-7,k0-7) t1=(m8-15,k0-7) t2=(m0-7,k8-15) t3=(m8-15,k8-15)
                int t = lane >> 3, ri = lane & 7;
                int row = wm + ma * 16 + (t & 1) * 8 + ri;
                int c   = 2 * kp + (t >> 1);
                uint32_t off = (uint32_t)(row * 32 + ((c ^ ((row >> 1) & 3)) << 3)) * 2;
                ldsm4(ah[ma][0], ah[ma][1], ah[ma][2], ah[ma][3], baseAh + off);
                ldsm4(al[ma][0], al[ma][1], al[ma][2], al[ma][3], baseAl + off);
            }
            #pragma unroll
            for (int np = 0; np < 4; np++) {
                // tiles: t0=(na0,b0) t1=(na0,b1) t2=(na1,b0) t3=(na1,b1)
                int t = lane >> 3, ri = lane & 7;
                int row = wn + np * 16 + (t >> 1) * 8 + ri;
                int c   = 2 * kp + (t & 1);
                uint32_t off = (uint32_t)(row * 32 + ((c ^ ((row >> 1) & 3)) << 3)) * 2;
                uint32_t bh[4], bl[4];
                ldsm4(bh[0], bh[1], bh[2], bh[3], baseBh + off);
                ldsm4(bl[0], bl[1], bl[2], bl[3], baseBl + off);
                #pragma unroll
                for (int sub = 0; sub < 2; sub++) {
                    int na = np * 2 + sub;
                    #pragma unroll
                    for (int ma = 0; ma < 2; ma++) {
                        mma_bf16(acc[ma][na], ah[ma], bh[sub * 2], bh[sub * 2 + 1]);
                        mma_bf16(acc[ma][na], ah[ma], bl[sub * 2], bl[sub * 2 + 1]);
                        mma_bf16(acc[ma][na], al[ma], bh[sub * 2], bh[sub * 2 + 1]);
                    }
                }
            }
        }
    };

    // ---- pipeline: register-prefetch ----
    load_tile(0);
    store_tile();
    __syncthreads();
    for (int s = 0;;) {
        if (s + 1 < nstages) load_tile((s + 1) * KT);
        compute();
        s++;
        if (s == nstages) break;
        __syncthreads();
        store_tile();
        __syncthreads();
    }

    // ---- epilogue ----
    #pragma unroll
    for (int ma = 0; ma < 2; ma++) {
        #pragma unroll
        for (int na = 0; na < 8; na++) {
            const int r0 = m0 + wm + ma * 16 + g;
            const int cb = n0 + wn + na * 8 + 2 * t4;
            float2 v0 = make_float2(acc[ma][na][0] * scale, acc[ma][na][1] * scale);
            float2 v1 = make_float2(acc[ma][na][2] * scale, acc[ma][na][3] * scale);
            float* p0 = &D[(size_t)r0 * ldd + cb];
            float* p1 = &D[(size_t)(r0 + 8) * ldd + cb];
            if (ACCUM) {
                float2 o0 = *(const float2*)p0;
                float2 o1 = *(const float2*)p1;
                v0.x += o0.x; v0.y += o0.y;
                v1.x += o1.x; v1.y += o1.y;
            }
            *(float2*)p0 = v0;
            *(float2*)p1 = v1;
        }
    }
}

// ---------------------------------------------------------------------------
// Softmax over last dim (M=1024), in place. One CTA of 256 per row.
// ---------------------------------------------------------------------------
__global__ void __launch_bounds__(256) softmax_kernel(float* __restrict__ E)
{
    float4* row = (float4*)(E + (size_t)blockIdx.x * MM);
    const int t = threadIdx.x;
    float4 v = row[t];

    __shared__ float rmax[8];
    __shared__ float rsum[8];

    float mx = fmaxf(fmaxf(v.x, v.y), fmaxf(v.z, v.w));
    #pragma unroll
    for (int o = 16; o > 0; o >>= 1)
        mx = fmaxf(mx, __shfl_xor_sync(0xffffffffu, mx, o));
    if ((t & 31) == 0) rmax[t >> 5] = mx;
    __syncthreads();
    mx = rmax[0];
    #pragma unroll
    for (int i = 1; i < 8; i++) mx = fmaxf(mx, rmax[i]);

    float e0 = __expf(v.x - mx);
    float e1 = __expf(v.y - mx);
    float e2 = __expf(v.z - mx);
    float e3 = __expf(v.w - mx);
    float s = e0 + e1 + e2 + e3;
    #pragma unroll
    for (int o = 16; o > 0; o >>= 1)
        s += __shfl_xor_sync(0xffffffffu, s, o);
    if ((t & 31) == 0) rsum[t >> 5] = s;
    __syncthreads();
    s = rsum[0];
    #pragma unroll
    for (int i = 1; i < 8; i++) s += rsum[i];

    float inv = 1.0f / s;
    row[t] = make_float4(e0 * inv, e1 * inv, e2 * inv, e3 * inv);
}

// ---------------------------------------------------------------------------
// Launch
// inputs: pcd_up [B,C,N], pcd_down [B,C,M], Wq, Wk, Wv, Wskip [C,C]
// output: [B,C,N] float32
// ---------------------------------------------------------------------------
extern "C" void kernel_launch(void* const* d_in, const int* in_sizes, int n_in,
                              void* d_out, int out_size)
{
    const float* pcd_up   = (const float*)d_in[0];
    const float* pcd_down = (const float*)d_in[1];
    const float* Wq       = (const float*)d_in[2];
    const float* Wk       = (const float*)d_in[3];
    const float* Wv       = (const float*)d_in[4];
    const float* Wskip    = (const float*)d_in[5];
    float* out = (float*)d_out;

    float *Tup, *Tdn, *Qt, *Kt, *V, *E;
    cudaGetSymbolAddress((void**)&Tup, g_Tup);
    cudaGetSymbolAddress((void**)&Tdn, g_Tdn);
    cudaGetSymbolAddress((void**)&Qt,  g_Qt);
    cudaGetSymbolAddress((void**)&Kt,  g_Kt);
    cudaGetSymbolAddress((void**)&V,   g_V);
    cudaGetSymbolAddress((void**)&E,   g_E);

    const float rscale = 0.04419417382415922f;  // 1/sqrt(512)
    const size_t sUC = (size_t)CC * NN;   // per-batch [C,N] / [N,C]
    const size_t sDC = (size_t)CC * MM;   // per-batch [C,M] / [M,C]
    const size_t sE  = (size_t)NN * MM;

    // 0) transposes: Tup[n][c], Tdn[m][c]
    transpose_kernel<<<dim3(NN / 32, CC / 32, BB), 256>>>(pcd_up,   Tup, CC, NN);
    transpose_kernel<<<dim3(MM / 32, CC / 32, BB), 256>>>(pcd_down, Tdn, CC, MM);

    // 1) Qt[n][o] = sum_c Tup[n][c] Wq[o][c]      (M=N, N=C, K=C)
    tc_gemm<false><<<dim3(CC / 128, NN / 128, BB), 256>>>(
        Tup, Wq, Qt, CC, CC, CC, sUC, 0, sUC, CC, 1.0f);
    // 2) Kt[m][o] = sum_c Tdn[m][c] Wk[o][c]      (M=M, N=C, K=C)
    tc_gemm<false><<<dim3(CC / 128, MM / 128, BB), 256>>>(
        Tdn, Wk, Kt, CC, CC, CC, sDC, 0, sDC, CC, 1.0f);
    // 3) V[o][m] = sum_c Wv[o][c] Tdn[m][c]       (M=C, N=M, K=C)
    tc_gemm<false><<<dim3(MM / 128, CC / 128, BB), 256>>>(
        Wv, Tdn, V, CC, CC, MM, 0, sDC, sDC, CC, 1.0f);
    // 4) out[o][n] = sum_c Wskip[o][c] Tup[n][c]  (M=C, N=N, K=C)
    tc_gemm<false><<<dim3(NN / 128, CC / 128, BB), 256>>>(
        Wskip, Tup, out, CC, CC, NN, 0, sUC, sUC, CC, 1.0f);

    // 5) E[n][m] = rscale * sum_c Qt[n][c] Kt[m][c]  (M=N, N=M, K=C)
    tc_gemm<false><<<dim3(MM / 128, NN / 128, BB), 256>>>(
        Qt, Kt, E, CC, CC, MM, sUC, sDC, sE, CC, rscale);

    // 6) softmax over M, in place
    softmax_kernel<<<BB * NN, 256>>>(E);

    // 7) out[c][n] += sum_m V[c][m] E[n][m]       (M=C, N=N, K=M)
    tc_gemm<true><<<dim3(NN / 128, CC / 128, BB), 256>>>(
        V, E, out, MM, MM, NN, sDC, sE, sUC, MM, 1.0f);
}

// round 5
// speedup vs baseline: 3.3771x; 1.4220x over previous
#include <cuda_runtime.h>
#include <cuda_bf16.h>
#include <cstdint>
#include <math.h>

// Problem constants
#define BB 8
#define CC 512
#define NN 4096
#define MM 1024

// ---------------------------------------------------------------------------
// Scratch: bf16 hi/lo plane pairs for every GEMM operand (no cudaMalloc).
// ---------------------------------------------------------------------------
__device__ __nv_bfloat16 g_TupH[(size_t)BB * NN * CC];  // pcd_up^T  [B][N][C]
__device__ __nv_bfloat16 g_TupL[(size_t)BB * NN * CC];
__device__ __nv_bfloat16 g_TdnH[(size_t)BB * MM * CC];  // pcd_down^T [B][M][C]
__device__ __nv_bfloat16 g_TdnL[(size_t)BB * MM * CC];
__device__ __nv_bfloat16 g_WqH[CC * CC], g_WqL[CC * CC];
__device__ __nv_bfloat16 g_WkH[CC * CC], g_WkL[CC * CC];
__device__ __nv_bfloat16 g_WvH[CC * CC], g_WvL[CC * CC];
__device__ __nv_bfloat16 g_WsH[CC * CC], g_WsL[CC * CC];
__device__ __nv_bfloat16 g_QtH[(size_t)BB * NN * CC];   // Q^T [B][N][C]
__device__ __nv_bfloat16 g_QtL[(size_t)BB * NN * CC];
__device__ __nv_bfloat16 g_KtH[(size_t)BB * MM * CC];   // K^T [B][M][C]
__device__ __nv_bfloat16 g_KtL[(size_t)BB * MM * CC];
__device__ __nv_bfloat16 g_VH [(size_t)BB * CC * MM];   // V [B][C][M]
__device__ __nv_bfloat16 g_VL [(size_t)BB * CC * MM];
__device__ float         g_E  [(size_t)BB * NN * MM];   // energy fp32
__device__ __nv_bfloat16 g_PH [(size_t)BB * NN * MM];   // attention planes
__device__ __nv_bfloat16 g_PL [(size_t)BB * NN * MM];

// ---------------------------------------------------------------------------
// helpers
// ---------------------------------------------------------------------------
__device__ __forceinline__ uint32_t smem_u32(const void* p) {
    uint32_t a;
    asm("{ .reg .u64 t; cvta.to.shared.u64 t, %1; cvt.u32.u64 %0, t; }"
        : "=r"(a) : "l"(p));
    return a;
}

__device__ __forceinline__ void split_bf16(float x, __nv_bfloat16& h, __nv_bfloat16& l) {
    h = __float2bfloat16_rn(x);
    l = __float2bfloat16_rn(x - __bfloat162float(h));
}

__device__ __forceinline__ void mma_bf16(float* c, const uint32_t* a,
                                         uint32_t b0, uint32_t b1) {
    asm volatile(
        "mma.sync.aligned.m16n8k16.row.col.f32.bf16.bf16.f32 "
        "{%0,%1,%2,%3}, {%4,%5,%6,%7}, {%8,%9}, {%0,%1,%2,%3};"
        : "+f"(c[0]), "+f"(c[1]), "+f"(c[2]), "+f"(c[3])
        : "r"(a[0]), "r"(a[1]), "r"(a[2]), "r"(a[3]), "r"(b0), "r"(b1));
}

__device__ __forceinline__ void ldsm4(uint32_t& r0, uint32_t& r1,
                                      uint32_t& r2, uint32_t& r3, uint32_t addr) {
    asm volatile("ldmatrix.sync.aligned.m8n8.x4.shared.b16 {%0,%1,%2,%3}, [%4];"
                 : "=r"(r0), "=r"(r1), "=r"(r2), "=r"(r3) : "r"(addr));
}

#define CP16(dst, src) \
    asm volatile("cp.async.ca.shared.global [%0], [%1], 16;" :: "r"(dst), "l"(src))
#define CP_COMMIT() asm volatile("cp.async.commit_group;" ::: "memory")
#define CP_WAIT1()  asm volatile("cp.async.wait_group 1;" ::: "memory")
#define CP_WAIT0()  asm volatile("cp.async.wait_group 0;" ::: "memory")

// ---------------------------------------------------------------------------
// transpose + split: in fp32 [rows, cols] per batch -> hi/lo bf16 [cols, rows]
// ---------------------------------------------------------------------------
__global__ void __launch_bounds__(256) transpose_split_kernel(
    const float* __restrict__ in, __nv_bfloat16* __restrict__ oh,
    __nv_bfloat16* __restrict__ ol, int rows, int cols)
{
    __shared__ float t[32][33];
    const int b = blockIdx.z;
    in += (size_t)b * rows * cols;
    oh += (size_t)b * rows * cols;
    ol += (size_t)b * rows * cols;
    const int r0 = blockIdx.y * 32, c0 = blockIdx.x * 32;
    const int tx = threadIdx.x & 31, ty = threadIdx.x >> 5;
    #pragma unroll
    for (int i = 0; i < 32; i += 8)
        t[ty + i][tx] = in[(size_t)(r0 + ty + i) * cols + c0 + tx];
    __syncthreads();
    #pragma unroll
    for (int i = 0; i < 32; i += 8) {
        float v = t[tx][ty + i];
        __nv_bfloat16 h, l;
        split_bf16(v, h, l);
        size_t o = (size_t)(c0 + ty + i) * rows + r0 + tx;
        oh[o] = h;
        ol[o] = l;
    }
}

// elementwise split for the weight matrices
__global__ void __launch_bounds__(256) split_kernel(
    const float* __restrict__ in, __nv_bfloat16* __restrict__ oh,
    __nv_bfloat16* __restrict__ ol, int n)
{
    int i = blockIdx.x * 256 + threadIdx.x;
    if (i < n) {
        __nv_bfloat16 h, l;
        split_bf16(in[i], h, l);
        oh[i] = h;
        ol[i] = l;
    }
}

// ---------------------------------------------------------------------------
// Tensor-core GEMM, bf16x3 fp32 emulation, pre-split bf16 plane inputs.
//   D[m, n] (tile 128x128) = scale * sum_k A[m][k] * B[n][k]
// OUTMODE: 0 = fp32 store, 1 = fp32 accumulate, 2 = split hi/lo bf16 store.
// cp.async 2-stage double buffer in dynamic smem (64 KB).
// Smem plane layout: 128 rows x 64 B, phys 16B-chunk = kc ^ ((row>>1)&3).
// ---------------------------------------------------------------------------
#define KT 32
#define PLANE 8192
#define STAGE 32768

template<int OUTMODE>
__global__ void __launch_bounds__(256, 2) tc_gemm(
    const __nv_bfloat16* __restrict__ AH, const __nv_bfloat16* __restrict__ AL,
    const __nv_bfloat16* __restrict__ BH, const __nv_bfloat16* __restrict__ BL,
    void* __restrict__ Dp, void* __restrict__ Dp2,
    int lda, int ldb, int ldd,
    size_t strA, size_t strB, size_t strD,
    int Kdim, float scale)
{
    extern __shared__ char smem[];
    const uint32_t sb = smem_u32(smem);

    const int tid  = threadIdx.x;
    const int wid  = tid >> 5;
    const int lane = tid & 31;
    const int g    = lane >> 2;
    const int t4   = lane & 3;
    const int wm   = (wid >> 1) * 32;
    const int wn   = (wid & 1) * 64;

    const int bz = blockIdx.z;
    const int m0 = blockIdx.y * 128;
    const int n0 = blockIdx.x * 128;

    AH += (size_t)bz * strA;  AL += (size_t)bz * strA;
    BH += (size_t)bz * strB;  BL += (size_t)bz * strB;

    float acc[2][8][4] = {};
    const int nstages = Kdim / KT;

    // ---- cp.async one KT stage (4 planes) into buffer buf ----
    auto stage_load = [&](int k0, int buf) {
        const uint32_t sbase = sb + buf * STAGE;
        #pragma unroll
        for (int i = 0; i < 2; i++) {
            int f = tid + i * 256;          // 0..511
            int row = f >> 2, kc = f & 3;
            uint32_t doff = (uint32_t)(row * 64 + ((kc ^ ((row >> 1) & 3)) << 4));
            size_t aoff = (size_t)(m0 + row) * lda + k0 + kc * 8;
            size_t boff = (size_t)(n0 + row) * ldb + k0 + kc * 8;
            CP16(sbase + doff,             AH + aoff);
            CP16(sbase + PLANE + doff,     AL + aoff);
            CP16(sbase + 2 * PLANE + doff, BH + boff);
            CP16(sbase + 3 * PLANE + doff, BL + boff);
        }
    };

    // ---- one KT stage of MMAs from buffer buf ----
    auto compute = [&](int buf) {
        const uint32_t bAh = sb + buf * STAGE;
        const uint32_t bAl = bAh + PLANE;
        const uint32_t bBh = bAh + 2 * PLANE;
        const uint32_t bBl = bAh + 3 * PLANE;
        #pragma unroll
        for (int kp = 0; kp < 2; kp++) {
            uint32_t ah[2][4], al[2][4];
            #pragma unroll
            for (int ma = 0; ma < 2; ma++) {
                int t = lane >> 3, ri = lane & 7;
                int row = wm + ma * 16 + (t & 1) * 8 + ri;
                int c   = 2 * kp + (t >> 1);
                uint32_t off = (uint32_t)(row * 32 + ((c ^ ((row >> 1) & 3)) << 3)) * 2;
                ldsm4(ah[ma][0], ah[ma][1], ah[ma][2], ah[ma][3], bAh + off);
                ldsm4(al[ma][0], al[ma][1], al[ma][2], al[ma][3], bAl + off);
            }
            #pragma unroll
            for (int np = 0; np < 4; np++) {
                int t = lane >> 3, ri = lane & 7;
                int row = wn + np * 16 + (t >> 1) * 8 + ri;
                int c   = 2 * kp + (t & 1);
                uint32_t off = (uint32_t)(row * 32 + ((c ^ ((row >> 1) & 3)) << 3)) * 2;
                uint32_t bh[4], bl[4];
                ldsm4(bh[0], bh[1], bh[2], bh[3], bBh + off);
                ldsm4(bl[0], bl[1], bl[2], bl[3], bBl + off);
                #pragma unroll
                for (int sub = 0; sub < 2; sub++) {
                    int na = np * 2 + sub;
                    #pragma unroll
                    for (int ma = 0; ma < 2; ma++) {
                        mma_bf16(acc[ma][na], ah[ma], bh[sub * 2], bh[sub * 2 + 1]);
                        mma_bf16(acc[ma][na], ah[ma], bl[sub * 2], bl[sub * 2 + 1]);
                        mma_bf16(acc[ma][na], al[ma], bh[sub * 2], bh[sub * 2 + 1]);
                    }
                }
            }
        }
    };

    // ---- software pipeline ----
    stage_load(0, 0);
    CP_COMMIT();
    for (int s = 0; s < nstages; s++) {
        if (s + 1 < nstages) {
            stage_load((s + 1) * KT, (s + 1) & 1);
            CP_COMMIT();
            CP_WAIT1();
        } else {
            CP_WAIT0();
        }
        __syncthreads();
        compute(s & 1);
        __syncthreads();
    }

    // ---- epilogue ----
    #pragma unroll
    for (int ma = 0; ma < 2; ma++) {
        #pragma unroll
        for (int na = 0; na < 8; na++) {
            const int r0 = m0 + wm + ma * 16 + g;
            const int cb = n0 + wn + na * 8 + 2 * t4;
            float v[4] = {acc[ma][na][0] * scale, acc[ma][na][1] * scale,
                          acc[ma][na][2] * scale, acc[ma][na][3] * scale};
            if (OUTMODE == 2) {
                __nv_bfloat16* Dh = (__nv_bfloat16*)Dp + (size_t)bz * strD;
                __nv_bfloat16* Dl = (__nv_bfloat16*)Dp2 + (size_t)bz * strD;
                #pragma unroll
                for (int hrow = 0; hrow < 2; hrow++) {
                    size_t o = (size_t)(r0 + hrow * 8) * ldd + cb;
                    __nv_bfloat16 h0, l0, h1, l1;
                    split_bf16(v[hrow * 2 + 0], h0, l0);
                    split_bf16(v[hrow * 2 + 1], h1, l1);
                    __nv_bfloat162 ph; ph.x = h0; ph.y = h1;
                    __nv_bfloat162 pl; pl.x = l0; pl.y = l1;
                    *(__nv_bfloat162*)&Dh[o] = ph;
                    *(__nv_bfloat162*)&Dl[o] = pl;
                }
            } else {
                float* D = (float*)Dp + (size_t)bz * strD;
                #pragma unroll
                for (int hrow = 0; hrow < 2; hrow++) {
                    float* p = &D[(size_t)(r0 + hrow * 8) * ldd + cb];
                    float2 w = make_float2(v[hrow * 2], v[hrow * 2 + 1]);
                    if (OUTMODE == 1) {
                        float2 o = *(const float2*)p;
                        w.x += o.x; w.y += o.y;
                    }
                    *(float2*)p = w;
                }
            }
        }
    }
}

// ---------------------------------------------------------------------------
// Softmax over last dim (M=1024): read fp32 E, write split hi/lo bf16 P.
// ---------------------------------------------------------------------------
__global__ void __launch_bounds__(256) softmax_split_kernel(
    const float* __restrict__ E, __nv_bfloat16* __restrict__ PH,
    __nv_bfloat16* __restrict__ PL)
{
    const size_t rb = (size_t)blockIdx.x * MM;
    const float4* row = (const float4*)(E + rb);
    const int t = threadIdx.x;
    float4 v = row[t];

    __shared__ float rmax[8];
    __shared__ float rsum[8];

    float mx = fmaxf(fmaxf(v.x, v.y), fmaxf(v.z, v.w));
    #pragma unroll
    for (int o = 16; o > 0; o >>= 1)
        mx = fmaxf(mx, __shfl_xor_sync(0xffffffffu, mx, o));
    if ((t & 31) == 0) rmax[t >> 5] = mx;
    __syncthreads();
    mx = rmax[0];
    #pragma unroll
    for (int i = 1; i < 8; i++) mx = fmaxf(mx, rmax[i]);

    float e[4];
    e[0] = __expf(v.x - mx);
    e[1] = __expf(v.y - mx);
    e[2] = __expf(v.z - mx);
    e[3] = __expf(v.w - mx);
    float s = e[0] + e[1] + e[2] + e[3];
    #pragma unroll
    for (int o = 16; o > 0; o >>= 1)
        s += __shfl_xor_sync(0xffffffffu, s, o);
    if ((t & 31) == 0) rsum[t >> 5] = s;
    __syncthreads();
    s = rsum[0];
    #pragma unroll
    for (int i = 1; i < 8; i++) s += rsum[i];

    const float inv = 1.0f / s;
    __nv_bfloat16 h[4], l[4];
    #pragma unroll
    for (int i = 0; i < 4; i++) split_bf16(e[i] * inv, h[i], l[i]);
    *(uint2*)&PH[rb + t * 4] = *(uint2*)h;
    *(uint2*)&PL[rb + t * 4] = *(uint2*)l;
}

// ---------------------------------------------------------------------------
// Launch
// ---------------------------------------------------------------------------
extern "C" void kernel_launch(void* const* d_in, const int* in_sizes, int n_in,
                              void* d_out, int out_size)
{
    const float* pcd_up   = (const float*)d_in[0];
    const float* pcd_down = (const float*)d_in[1];
    const float* Wq       = (const float*)d_in[2];
    const float* Wk       = (const float*)d_in[3];
    const float* Wv       = (const float*)d_in[4];
    const float* Wskip    = (const float*)d_in[5];
    float* out = (float*)d_out;

    __nv_bfloat16 *TupH, *TupL, *TdnH, *TdnL, *WqH, *WqL, *WkH, *WkL;
    __nv_bfloat16 *WvH, *WvL, *WsH, *WsL, *QtH, *QtL, *KtH, *KtL, *VH, *VL, *PH, *PL;
    float* E;
    cudaGetSymbolAddress((void**)&TupH, g_TupH);
    cudaGetSymbolAddress((void**)&TupL, g_TupL);
    cudaGetSymbolAddress((void**)&TdnH, g_TdnH);
    cudaGetSymbolAddress((void**)&TdnL, g_TdnL);
    cudaGetSymbolAddress((void**)&WqH, g_WqH);
    cudaGetSymbolAddress((void**)&WqL, g_WqL);
    cudaGetSymbolAddress((void**)&WkH, g_WkH);
    cudaGetSymbolAddress((void**)&WkL, g_WkL);
    cudaGetSymbolAddress((void**)&WvH, g_WvH);
    cudaGetSymbolAddress((void**)&WvL, g_WvL);
    cudaGetSymbolAddress((void**)&WsH, g_WsH);
    cudaGetSymbolAddress((void**)&WsL, g_WsL);
    cudaGetSymbolAddress((void**)&QtH, g_QtH);
    cudaGetSymbolAddress((void**)&QtL, g_QtL);
    cudaGetSymbolAddress((void**)&KtH, g_KtH);
    cudaGetSymbolAddress((void**)&KtL, g_KtL);
    cudaGetSymbolAddress((void**)&VH, g_VH);
    cudaGetSymbolAddress((void**)&VL, g_VL);
    cudaGetSymbolAddress((void**)&PH, g_PH);
    cudaGetSymbolAddress((void**)&PL, g_PL);
    cudaGetSymbolAddress((void**)&E, g_E);

    static bool attr_done = false;
    if (!attr_done) {
        cudaFuncSetAttribute(tc_gemm<0>, cudaFuncAttributeMaxDynamicSharedMemorySize, 65536);
        cudaFuncSetAttribute(tc_gemm<1>, cudaFuncAttributeMaxDynamicSharedMemorySize, 65536);
        cudaFuncSetAttribute(tc_gemm<2>, cudaFuncAttributeMaxDynamicSharedMemorySize, 65536);
        attr_done = true;
    }

    const float rscale = 0.04419417382415922f;  // 1/sqrt(512)
    const size_t sNC = (size_t)NN * CC;
    const size_t sMC = (size_t)MM * CC;
    const size_t sE  = (size_t)NN * MM;

    // 0) transpose + split inputs; split weights
    transpose_split_kernel<<<dim3(NN / 32, CC / 32, BB), 256>>>(pcd_up, TupH, TupL, CC, NN);
    transpose_split_kernel<<<dim3(MM / 32, CC / 32, BB), 256>>>(pcd_down, TdnH, TdnL, CC, MM);
    split_kernel<<<CC * CC / 256, 256>>>(Wq, WqH, WqL, CC * CC);
    split_kernel<<<CC * CC / 256, 256>>>(Wk, WkH, WkL, CC * CC);
    split_kernel<<<CC * CC / 256, 256>>>(Wv, WvH, WvL, CC * CC);
    split_kernel<<<CC * CC / 256, 256>>>(Wskip, WsH, WsL, CC * CC);

    // 1) Qt[n][o] = sum_c Tup[n][c] Wq[o][c]          -> split planes
    tc_gemm<2><<<dim3(CC / 128, NN / 128, BB), 256, 65536>>>(
        TupH, TupL, WqH, WqL, QtH, QtL, CC, CC, CC, sNC, 0, sNC, CC, 1.0f);
    // 2) Kt[m][o] = sum_c Tdn[m][c] Wk[o][c]          -> split planes
    tc_gemm<2><<<dim3(CC / 128, MM / 128, BB), 256, 65536>>>(
        TdnH, TdnL, WkH, WkL, KtH, KtL, CC, CC, CC, sMC, 0, sMC, CC, 1.0f);
    // 3) V[o][m] = sum_c Wv[o][c] Tdn[m][c]           -> split planes
    tc_gemm<2><<<dim3(MM / 128, CC / 128, BB), 256, 65536>>>(
        WvH, WvL, TdnH, TdnL, VH, VL, CC, CC, MM, 0, sMC, sMC, CC, 1.0f);
    // 4) out[o][n] = sum_c Wskip[o][c] Tup[n][c]      -> fp32 out
    tc_gemm<0><<<dim3(NN / 128, CC / 128, BB), 256, 65536>>>(
        WsH, WsL, TupH, TupL, out, nullptr, CC, CC, NN, 0, sNC, sNC, CC, 1.0f);

    // 5) E[n][m] = rscale * sum_c Qt[n][c] Kt[m][c]   -> fp32
    tc_gemm<0><<<dim3(MM / 128, NN / 128, BB), 256, 65536>>>(
        QtH, QtL, KtH, KtL, E, nullptr, CC, CC, MM, sNC, sMC, sE, CC, rscale);

    // 6) softmax over M -> split P planes
    softmax_split_kernel<<<BB * NN, 256>>>(E, PH, PL);

    // 7) out[c][n] += sum_m V[c][m] P[n][m]
    tc_gemm<1><<<dim3(NN / 128, CC / 128, BB), 256, 65536>>>(
        VH, VL, PH, PL, out, nullptr, MM, MM, NN, sMC, sE, sNC, MM, 1.0f);
}

// round 6
// speedup vs baseline: 3.7161x; 1.1004x over previous
#include <cuda_runtime.h>
#include <cuda_bf16.h>
#include <cstdint>
#include <math.h>

// Problem constants
#define BB 8
#define CC 512
#define NN 4096
#define MM 1024

// ---------------------------------------------------------------------------
// Scratch: bf16 hi/lo plane pairs for every GEMM operand (no cudaMalloc).
// ---------------------------------------------------------------------------
__device__ __nv_bfloat16 g_TupH[(size_t)BB * NN * CC];  // pcd_up^T  [B][N][C]
__device__ __nv_bfloat16 g_TupL[(size_t)BB * NN * CC];
__device__ __nv_bfloat16 g_TdnH[(size_t)BB * MM * CC];  // pcd_down^T [B][M][C]
__device__ __nv_bfloat16 g_TdnL[(size_t)BB * MM * CC];
__device__ __nv_bfloat16 g_WqH[CC * CC], g_WqL[CC * CC];
__device__ __nv_bfloat16 g_WkH[CC * CC], g_WkL[CC * CC];
__device__ __nv_bfloat16 g_WvH[CC * CC], g_WvL[CC * CC];
__device__ __nv_bfloat16 g_WsH[CC * CC], g_WsL[CC * CC];
__device__ __nv_bfloat16 g_QtH[(size_t)BB * NN * CC];   // Q^T [B][N][C]
__device__ __nv_bfloat16 g_QtL[(size_t)BB * NN * CC];
__device__ __nv_bfloat16 g_KtH[(size_t)BB * MM * CC];   // K^T [B][M][C]
__device__ __nv_bfloat16 g_KtL[(size_t)BB * MM * CC];
__device__ __nv_bfloat16 g_VH [(size_t)BB * CC * MM];   // V [B][C][M]
__device__ __nv_bfloat16 g_VL [(size_t)BB * CC * MM];
__device__ float         g_E  [(size_t)BB * NN * MM];   // energy fp32
__device__ __nv_bfloat16 g_PH [(size_t)BB * NN * MM];   // attention planes
__device__ __nv_bfloat16 g_PL [(size_t)BB * NN * MM];

// ---------------------------------------------------------------------------
// helpers
// ---------------------------------------------------------------------------
__device__ __forceinline__ uint32_t smem_u32(const void* p) {
    uint32_t a;
    asm("{ .reg .u64 t; cvta.to.shared.u64 t, %1; cvt.u32.u64 %0, t; }"
        : "=r"(a) : "l"(p));
    return a;
}

__device__ __forceinline__ void split_bf16(float x, __nv_bfloat16& h, __nv_bfloat16& l) {
    h = __float2bfloat16_rn(x);
    l = __float2bfloat16_rn(x - __bfloat162float(h));
}

__device__ __forceinline__ void mma_bf16(float* c, const uint32_t* a,
                                         uint32_t b0, uint32_t b1) {
    asm volatile(
        "mma.sync.aligned.m16n8k16.row.col.f32.bf16.bf16.f32 "
        "{%0,%1,%2,%3}, {%4,%5,%6,%7}, {%8,%9}, {%0,%1,%2,%3};"
        : "+f"(c[0]), "+f"(c[1]), "+f"(c[2]), "+f"(c[3])
        : "r"(a[0]), "r"(a[1]), "r"(a[2]), "r"(a[3]), "r"(b0), "r"(b1));
}

__device__ __forceinline__ void ldsm4(uint32_t& r0, uint32_t& r1,
                                      uint32_t& r2, uint32_t& r3, uint32_t addr) {
    asm volatile("ldmatrix.sync.aligned.m8n8.x4.shared.b16 {%0,%1,%2,%3}, [%4];"
                 : "=r"(r0), "=r"(r1), "=r"(r2), "=r"(r3) : "r"(addr));
}

#define CP16(dst, src) \
    asm volatile("cp.async.cg.shared.global [%0], [%1], 16;" :: "r"(dst), "l"(src))
#define CP_COMMIT() asm volatile("cp.async.commit_group;" ::: "memory")
#define CP_WAIT1()  asm volatile("cp.async.wait_group 1;" ::: "memory")
#define CP_WAIT0()  asm volatile("cp.async.wait_group 0;" ::: "memory")

// ---------------------------------------------------------------------------
// transpose + split: in fp32 [rows, cols] per batch -> hi/lo bf16 [cols, rows]
// ---------------------------------------------------------------------------
__global__ void __launch_bounds__(256) transpose_split_kernel(
    const float* __restrict__ in, __nv_bfloat16* __restrict__ oh,
    __nv_bfloat16* __restrict__ ol, int rows, int cols)
{
    __shared__ float t[32][33];
    const int b = blockIdx.z;
    in += (size_t)b * rows * cols;
    oh += (size_t)b * rows * cols;
    ol += (size_t)b * rows * cols;
    const int r0 = blockIdx.y * 32, c0 = blockIdx.x * 32;
    const int tx = threadIdx.x & 31, ty = threadIdx.x >> 5;
    #pragma unroll
    for (int i = 0; i < 32; i += 8)
        t[ty + i][tx] = in[(size_t)(r0 + ty + i) * cols + c0 + tx];
    __syncthreads();
    #pragma unroll
    for (int i = 0; i < 32; i += 8) {
        float v = t[tx][ty + i];
        __nv_bfloat16 h, l;
        split_bf16(v, h, l);
        size_t o = (size_t)(c0 + ty + i) * rows + r0 + tx;
        oh[o] = h;
        ol[o] = l;
    }
}

// elementwise split for the weight matrices
__global__ void __launch_bounds__(256) split_kernel(
    const float* __restrict__ in, __nv_bfloat16* __restrict__ oh,
    __nv_bfloat16* __restrict__ ol, int n)
{
    int i = blockIdx.x * 256 + threadIdx.x;
    if (i < n) {
        __nv_bfloat16 h, l;
        split_bf16(in[i], h, l);
        oh[i] = h;
        ol[i] = l;
    }
}

// ---------------------------------------------------------------------------
// Tensor-core GEMM, bf16x3 fp32 emulation, pre-split bf16 plane inputs.
//   D[m, n] (tile 128x128) = scale * sum_k A[m][k] * B[n][k]
// OUTMODE: 0 = fp32 store, 1 = fp32 accumulate, 2 = split hi/lo bf16 store.
// cp.async 3-stage ring in dynamic smem (96 KB), ONE __syncthreads per stage.
// Smem plane layout: 128 rows x 64 B, phys 16B-chunk = kc ^ ((row>>1)&3).
// ---------------------------------------------------------------------------
#define KT 32
#define PLANE 8192
#define STAGE 32768
#define SMEMBYTES (3 * STAGE)

template<int OUTMODE>
__global__ void __launch_bounds__(256, 2) tc_gemm(
    const __nv_bfloat16* __restrict__ AH, const __nv_bfloat16* __restrict__ AL,
    const __nv_bfloat16* __restrict__ BH, const __nv_bfloat16* __restrict__ BL,
    void* __restrict__ Dp, void* __restrict__ Dp2,
    int lda, int ldb, int ldd,
    size_t strA, size_t strB, size_t strD,
    int Kdim, float scale)
{
    extern __shared__ char smem[];
    const uint32_t sb = smem_u32(smem);

    const int tid  = threadIdx.x;
    const int wid  = tid >> 5;
    const int lane = tid & 31;
    const int g    = lane >> 2;
    const int t4   = lane & 3;
    const int wm   = (wid >> 1) * 32;
    const int wn   = (wid & 1) * 64;

    const int bz = blockIdx.z;
    const int m0 = blockIdx.y * 128;
    const int n0 = blockIdx.x * 128;

    AH += (size_t)bz * strA;  AL += (size_t)bz * strA;
    BH += (size_t)bz * strB;  BL += (size_t)bz * strB;

    float acc[2][8][4] = {};
    const int nstages = Kdim / KT;

    // ---- cp.async one KT stage (4 planes) into ring buffer buf ----
    auto stage_load = [&](int k0, int buf) {
        const uint32_t sbase = sb + buf * STAGE;
        #pragma unroll
        for (int i = 0; i < 2; i++) {
            int f = tid + i * 256;          // 0..511
            int row = f >> 2, kc = f & 3;
            uint32_t doff = (uint32_t)(row * 64 + ((kc ^ ((row >> 1) & 3)) << 4));
            size_t aoff = (size_t)(m0 + row) * lda + k0 + kc * 8;
            size_t boff = (size_t)(n0 + row) * ldb + k0 + kc * 8;
            CP16(sbase + doff,             AH + aoff);
            CP16(sbase + PLANE + doff,     AL + aoff);
            CP16(sbase + 2 * PLANE + doff, BH + boff);
            CP16(sbase + 3 * PLANE + doff, BL + boff);
        }
    };

    // ---- one KT stage of MMAs from ring buffer buf ----
    auto compute = [&](int buf) {
        const uint32_t bAh = sb + buf * STAGE;
        const uint32_t bAl = bAh + PLANE;
        const uint32_t bBh = bAh + 2 * PLANE;
        const uint32_t bBl = bAh + 3 * PLANE;
        const int t = lane >> 3, ri = lane & 7;
        #pragma unroll
        for (int kp = 0; kp < 2; kp++) {
            uint32_t ah[2][4], al[2][4];
            #pragma unroll
            for (int ma = 0; ma < 2; ma++) {
                int row = wm + ma * 16 + (t & 1) * 8 + ri;
                int c   = 2 * kp + (t >> 1);
                uint32_t off = (uint32_t)(row * 32 + ((c ^ ((row >> 1) & 3)) << 3)) * 2;
                ldsm4(ah[ma][0], ah[ma][1], ah[ma][2], ah[ma][3], bAh + off);
                ldsm4(al[ma][0], al[ma][1], al[ma][2], al[ma][3], bAl + off);
            }
            #pragma unroll
            for (int np = 0; np < 4; np++) {
                int row = wn + np * 16 + (t >> 1) * 8 + ri;
                int c   = 2 * kp + (t & 1);
                uint32_t off = (uint32_t)(row * 32 + ((c ^ ((row >> 1) & 3)) << 3)) * 2;
                uint32_t bh[4], bl[4];
                ldsm4(bh[0], bh[1], bh[2], bh[3], bBh + off);
                ldsm4(bl[0], bl[1], bl[2], bl[3], bBl + off);
                #pragma unroll
                for (int sub = 0; sub < 2; sub++) {
                    int na = np * 2 + sub;
                    #pragma unroll
                    for (int ma = 0; ma < 2; ma++) {
                        mma_bf16(acc[ma][na], ah[ma], bh[sub * 2], bh[sub * 2 + 1]);
                        mma_bf16(acc[ma][na], ah[ma], bl[sub * 2], bl[sub * 2 + 1]);
                        mma_bf16(acc[ma][na], al[ma], bh[sub * 2], bh[sub * 2 + 1]);
                    }
                }
            }
        }
    };

    // ---- software pipeline: 3-deep ring, one barrier per stage ----
    stage_load(0, 0);
    CP_COMMIT();
    stage_load(KT, 1);
    CP_COMMIT();

    int buf = 0, nbuf = 2;
    for (int s = 0; s < nstages; s++) {
        if (s + 1 < nstages) CP_WAIT1(); else CP_WAIT0();
        __syncthreads();     // publish stage s; also fences recycled buffer
        if (s + 2 < nstages) {
            // writes buffer computed at stage s-1 — all warps past it (barrier)
            stage_load((s + 2) * KT, nbuf);
            CP_COMMIT();
        }
        compute(buf);
        buf = (buf == 2) ? 0 : buf + 1;
        nbuf = (nbuf == 2) ? 0 : nbuf + 1;
    }

    // ---- epilogue ----
    #pragma unroll
    for (int ma = 0; ma < 2; ma++) {
        #pragma unroll
        for (int na = 0; na < 8; na++) {
            const int r0 = m0 + wm + ma * 16 + g;
            const int cb = n0 + wn + na * 8 + 2 * t4;
            float v[4] = {acc[ma][na][0] * scale, acc[ma][na][1] * scale,
                          acc[ma][na][2] * scale, acc[ma][na][3] * scale};
            if (OUTMODE == 2) {
                __nv_bfloat16* Dh = (__nv_bfloat16*)Dp + (size_t)bz * strD;
                __nv_bfloat16* Dl = (__nv_bfloat16*)Dp2 + (size_t)bz * strD;
                #pragma unroll
                for (int hrow = 0; hrow < 2; hrow++) {
                    size_t o = (size_t)(r0 + hrow * 8) * ldd + cb;
                    __nv_bfloat16 h0, l0, h1, l1;
                    split_bf16(v[hrow * 2 + 0], h0, l0);
                    split_bf16(v[hrow * 2 + 1], h1, l1);
                    __nv_bfloat162 ph; ph.x = h0; ph.y = h1;
                    __nv_bfloat162 pl; pl.x = l0; pl.y = l1;
                    *(__nv_bfloat162*)&Dh[o] = ph;
                    *(__nv_bfloat162*)&Dl[o] = pl;
                }
            } else {
                float* D = (float*)Dp + (size_t)bz * strD;
                #pragma unroll
                for (int hrow = 0; hrow < 2; hrow++) {
                    float* p = &D[(size_t)(r0 + hrow * 8) * ldd + cb];
                    float2 w = make_float2(v[hrow * 2], v[hrow * 2 + 1]);
                    if (OUTMODE == 1) {
                        float2 o = *(const float2*)p;
                        w.x += o.x; w.y += o.y;
                    }
                    *(float2*)p = w;
                }
            }
        }
    }
}

// ---------------------------------------------------------------------------
// Softmax over last dim (M=1024): read fp32 E, write split hi/lo bf16 P.
// ---------------------------------------------------------------------------
__global__ void __launch_bounds__(256) softmax_split_kernel(
    const float* __restrict__ E, __nv_bfloat16* __restrict__ PH,
    __nv_bfloat16* __restrict__ PL)
{
    const size_t rb = (size_t)blockIdx.x * MM;
    const float4* row = (const float4*)(E + rb);
    const int t = threadIdx.x;
    float4 v = row[t];

    __shared__ float rmax[8];
    __shared__ float rsum[8];

    float mx = fmaxf(fmaxf(v.x, v.y), fmaxf(v.z, v.w));
    #pragma unroll
    for (int o = 16; o > 0; o >>= 1)
        mx = fmaxf(mx, __shfl_xor_sync(0xffffffffu, mx, o));
    if ((t & 31) == 0) rmax[t >> 5] = mx;
    __syncthreads();
    mx = rmax[0];
    #pragma unroll
    for (int i = 1; i < 8; i++) mx = fmaxf(mx, rmax[i]);

    float e[4];
    e[0] = __expf(v.x - mx);
    e[1] = __expf(v.y - mx);
    e[2] = __expf(v.z - mx);
    e[3] = __expf(v.w - mx);
    float s = e[0] + e[1] + e[2] + e[3];
    #pragma unroll
    for (int o = 16; o > 0; o >>= 1)
        s += __shfl_xor_sync(0xffffffffu, s, o);
    if ((t & 31) == 0) rsum[t >> 5] = s;
    __syncthreads();
    s = rsum[0];
    #pragma unroll
    for (int i = 1; i < 8; i++) s += rsum[i];

    const float inv = 1.0f / s;
    __nv_bfloat16 h[4], l[4];
    #pragma unroll
    for (int i = 0; i < 4; i++) split_bf16(e[i] * inv, h[i], l[i]);
    *(uint2*)&PH[rb + t * 4] = *(uint2*)h;
    *(uint2*)&PL[rb + t * 4] = *(uint2*)l;
}

// ---------------------------------------------------------------------------
// Launch
// ---------------------------------------------------------------------------
extern "C" void kernel_launch(void* const* d_in, const int* in_sizes, int n_in,
                              void* d_out, int out_size)
{
    const float* pcd_up   = (const float*)d_in[0];
    const float* pcd_down = (const float*)d_in[1];
    const float* Wq       = (const float*)d_in[2];
    const float* Wk       = (const float*)d_in[3];
    const float* Wv       = (const float*)d_in[4];
    const float* Wskip    = (const float*)d_in[5];
    float* out = (float*)d_out;

    __nv_bfloat16 *TupH, *TupL, *TdnH, *TdnL, *WqH, *WqL, *WkH, *WkL;
    __nv_bfloat16 *WvH, *WvL, *WsH, *WsL, *QtH, *QtL, *KtH, *KtL, *VH, *VL, *PH, *PL;
    float* E;
    cudaGetSymbolAddress((void**)&TupH, g_TupH);
    cudaGetSymbolAddress((void**)&TupL, g_TupL);
    cudaGetSymbolAddress((void**)&TdnH, g_TdnH);
    cudaGetSymbolAddress((void**)&TdnL, g_TdnL);
    cudaGetSymbolAddress((void**)&WqH, g_WqH);
    cudaGetSymbolAddress((void**)&WqL, g_WqL);
    cudaGetSymbolAddress((void**)&WkH, g_WkH);
    cudaGetSymbolAddress((void**)&WkL, g_WkL);
    cudaGetSymbolAddress((void**)&WvH, g_WvH);
    cudaGetSymbolAddress((void**)&WvL, g_WvL);
    cudaGetSymbolAddress((void**)&WsH, g_WsH);
    cudaGetSymbolAddress((void**)&WsL, g_WsL);
    cudaGetSymbolAddress((void**)&QtH, g_QtH);
    cudaGetSymbolAddress((void**)&QtL, g_QtL);
    cudaGetSymbolAddress((void**)&KtH, g_KtH);
    cudaGetSymbolAddress((void**)&KtL, g_KtL);
    cudaGetSymbolAddress((void**)&VH, g_VH);
    cudaGetSymbolAddress((void**)&VL, g_VL);
    cudaGetSymbolAddress((void**)&PH, g_PH);
    cudaGetSymbolAddress((void**)&PL, g_PL);
    cudaGetSymbolAddress((void**)&E, g_E);

    static bool attr_done = false;
    if (!attr_done) {
        cudaFuncSetAttribute(tc_gemm<0>, cudaFuncAttributeMaxDynamicSharedMemorySize, SMEMBYTES);
        cudaFuncSetAttribute(tc_gemm<1>, cudaFuncAttributeMaxDynamicSharedMemorySize, SMEMBYTES);
        cudaFuncSetAttribute(tc_gemm<2>, cudaFuncAttributeMaxDynamicSharedMemorySize, SMEMBYTES);
        attr_done = true;
    }

    const float rscale = 0.04419417382415922f;  // 1/sqrt(512)
    const size_t sNC = (size_t)NN * CC;
    const size_t sMC = (size_t)MM * CC;
    const size_t sE  = (size_t)NN * MM;

    // 0) transpose + split inputs; split weights
    transpose_split_kernel<<<dim3(NN / 32, CC / 32, BB), 256>>>(pcd_up, TupH, TupL, CC, NN);
    transpose_split_kernel<<<dim3(MM / 32, CC / 32, BB), 256>>>(pcd_down, TdnH, TdnL, CC, MM);
    split_kernel<<<CC * CC / 256, 256>>>(Wq, WqH, WqL, CC * CC);
    split_kernel<<<CC * CC / 256, 256>>>(Wk, WkH, WkL, CC * CC);
    split_kernel<<<CC * CC / 256, 256>>>(Wv, WvH, WvL, CC * CC);
    split_kernel<<<CC * CC / 256, 256>>>(Wskip, WsH, WsL, CC * CC);

    // 1) Qt[n][o] = sum_c Tup[n][c] Wq[o][c]          -> split planes
    tc_gemm<2><<<dim3(CC / 128, NN / 128, BB), 256, SMEMBYTES>>>(
        TupH, TupL, WqH, WqL, QtH, QtL, CC, CC, CC, sNC, 0, sNC, CC, 1.0f);
    // 2) Kt[m][o] = sum_c Tdn[m][c] Wk[o][c]          -> split planes
    tc_gemm<2><<<dim3(CC / 128, MM / 128, BB), 256, SMEMBYTES>>>(
        TdnH, TdnL, WkH, WkL, KtH, KtL, CC, CC, CC, sMC, 0, sMC, CC, 1.0f);
    // 3) V[o][m] = sum_c Wv[o][c] Tdn[m][c]           -> split planes
    tc_gemm<2><<<dim3(MM / 128, CC / 128, BB), 256, SMEMBYTES>>>(
        WvH, WvL, TdnH, TdnL, VH, VL, CC, CC, MM, 0, sMC, sMC, CC, 1.0f);
    // 4) out[o][n] = sum_c Wskip[o][c] Tup[n][c]      -> fp32 out
    tc_gemm<0><<<dim3(NN / 128, CC / 128, BB), 256, SMEMBYTES>>>(
        WsH, WsL, TupH, TupL, out, nullptr, CC, CC, NN, 0, sNC, sNC, CC, 1.0f);

    // 5) E[n][m] = rscale * sum_c Qt[n][c] Kt[m][c]   -> fp32
    tc_gemm<0><<<dim3(MM / 128, NN / 128, BB), 256, SMEMBYTES>>>(
        QtH, QtL, KtH, KtL, E, nullptr, CC, CC, MM, sNC, sMC, sE, CC, rscale);

    // 6) softmax over M -> split P planes
    softmax_split_kernel<<<BB * NN, 256>>>(E, PH, PL);

    // 7) out[c][n] += sum_m V[c][m] P[n][m]
    tc_gemm<1><<<dim3(NN / 128, CC / 128, BB), 256, SMEMBYTES>>>(
        VH, VL, PH, PL, out, nullptr, MM, MM, NN, sMC, sE, sNC, MM, 1.0f);
}